// round 6
// baseline (speedup 1.0000x reference)
#include <cuda_runtime.h>
#include <cuda_bf16.h>
#include <cstdint>

#define VOCAB   1000000
#define EMB     50
#define OUTD    2
#define BATCH   128
#define SEQ     2000

#define NCHUNK  25                   // seq split
#define TOK     (SEQ / NCHUNK)       // 80 tokens per block
#define WARPS   8                    // 256 threads
#define TOK_PER_WARP (TOK / WARPS)   // 10
#define TOTAL_BLOCKS (BATCH * NCHUNK)

// Per-block projected partials: [chunk][batch][2]
__device__ float g_dots[NCHUNK * BATCH * OUTD];
__device__ unsigned int g_count = 0;

// ---------------------------------------------------------------------------
// Single fused kernel: gather + partial sum + [50->2] projection; the LAST
// block (fence+counter) performs the deterministic chunk reduction, /BATCH,
// +bias, ReLU, and writes the output. Counter self-resets for graph replay.
// grid = (BATCH, NCHUNK), block = 256 (8 warps).
// ---------------------------------------------------------------------------
__global__ __launch_bounds__(256)
void fused_kernel(const int* __restrict__ t,
                  const float* __restrict__ emb,
                  const float* __restrict__ W,
                  const float* __restrict__ bias,
                  float* __restrict__ out)
{
    const int b     = blockIdx.x;
    const int chunk = blockIdx.y;
    const int tid   = threadIdx.x;
    const int wid   = tid >> 5;
    const int lane  = tid & 31;

    __shared__ int    sidx[TOK];
    __shared__ float2 sred[WARPS][25];
    __shared__ bool   s_is_last;

    const int* tp = t + (size_t)b * SEQ + (size_t)chunk * TOK;
    if (tid < TOK) sidx[tid] = tp[tid];
    __syncthreads();

    const float2* __restrict__ emb2 = (const float2*)emb;

    float2 acc = make_float2(0.0f, 0.0f);
    if (lane < 25) {
        #pragma unroll
        for (int i = 0; i < TOK_PER_WARP; i++) {
            int idx = sidx[wid * TOK_PER_WARP + i];
            if (idx >= 0 && idx < VOCAB) {
                float2 v = __ldg(&emb2[(size_t)idx * 25 + lane]);
                acc.x += v.x;
                acc.y += v.y;
            }
        }
        sred[wid][lane] = acc;
    }
    __syncthreads();

    // Warp 0: reduce 8 warps, project onto the two W rows, warp-reduce, store.
    if (tid < 32) {
        float d0 = 0.0f, d1 = 0.0f;
        if (tid < 25) {
            float2 p = make_float2(0.0f, 0.0f);
            #pragma unroll
            for (int w = 0; w < WARPS; w++) {
                p.x += sred[w][tid].x;
                p.y += sred[w][tid].y;
            }
            d0 = p.x * W[2 * tid]       + p.y * W[2 * tid + 1];      // row 0
            d1 = p.x * W[EMB + 2 * tid] + p.y * W[EMB + 2 * tid + 1];// row 1
        }
        #pragma unroll
        for (int off = 16; off > 0; off >>= 1) {
            d0 += __shfl_down_sync(0xFFFFFFFFu, d0, off);
            d1 += __shfl_down_sync(0xFFFFFFFFu, d1, off);
        }
        if (tid == 0) {
            g_dots[((size_t)chunk * BATCH + b) * OUTD + 0] = d0;
            g_dots[((size_t)chunk * BATCH + b) * OUTD + 1] = d1;
        }
    }

    // ---- last-block finalize (fence + counter) ----
    __threadfence();            // make g_dots writes visible device-wide
    __syncthreads();
    if (tid == 0) {
        unsigned int v = atomicAdd(&g_count, 1u);
        s_is_last = (v == TOTAL_BLOCKS - 1);
    }
    __syncthreads();

    if (s_is_last) {
        // 256 threads == BATCH*OUTD outputs; fixed-order sum (deterministic).
        const int o = tid & 1;
        float s = 0.0f;
        #pragma unroll
        for (int k = 0; k < NCHUNK; k++) {
            s += __ldcg(&g_dots[(size_t)k * BATCH * OUTD + tid]);
        }
        out[tid] = fmaxf(s * (1.0f / (float)BATCH) + bias[o], 0.0f);

        __syncthreads();
        if (tid == 0) g_count = 0;   // reset for next graph replay
    }
}

// ---------------------------------------------------------------------------
// Inputs: t [128,2000] int32, embeddings [1e6,50] f32, W [2,50] f32, b [2] f32.
// Output: [128,2] f32.
// ---------------------------------------------------------------------------
extern "C" void kernel_launch(void* const* d_in, const int* in_sizes, int n_in,
                              void* d_out, int out_size)
{
    const int*   t   = (const int*)d_in[0];
    const float* emb = (const float*)d_in[1];
    const float* W   = (const float*)d_in[2];
    const float* bia = (const float*)d_in[3];
    float*       out = (float*)d_out;

    dim3 grid(BATCH, NCHUNK);
    fused_kernel<<<grid, 256>>>(t, emb, W, bia, out);
}

// round 7
// speedup vs baseline: 1.2623x; 1.2623x over previous
#include <cuda_runtime.h>
#include <cuda_bf16.h>
#include <cstdint>

#define VOCAB   1000000
#define EMB     50
#define OUTD    2
#define BATCH   128
#define SEQ     2000

#define NCHUNK  25                   // seq split
#define TOK     (SEQ / NCHUNK)       // 80 tokens per block
#define WARPS   8                    // 256 threads
#define TOK_PER_WARP (TOK / WARPS)   // 10

// Per-block projected partials: [chunk][batch][2]
__device__ float g_dots[NCHUNK * BATCH * OUTD];

// ---------------------------------------------------------------------------
// Kernel 1: gather + partial sum + [50 -> 2] projection.
// grid = (BATCH, NCHUNK), block = 256 (8 warps).
// Each warp owns 10 tokens; lanes 0-24 load the 50-float row as 25 float2.
// Signals programmatic launch completion so the finalize kernel's ramp
// overlaps the gather.
// ---------------------------------------------------------------------------
__global__ __launch_bounds__(256)
void gather_kernel(const int* __restrict__ t,
                   const float* __restrict__ emb,
                   const float* __restrict__ W)
{
    const int b     = blockIdx.x;
    const int chunk = blockIdx.y;
    const int tid   = threadIdx.x;
    const int wid   = tid >> 5;
    const int lane  = tid & 31;

    __shared__ int    sidx[TOK];
    __shared__ float2 sred[WARPS][25];

    const int* tp = t + (size_t)b * SEQ + (size_t)chunk * TOK;
    if (tid < TOK) sidx[tid] = tp[tid];
    __syncthreads();

    // PDL: allow the dependent (finalize) kernel to begin launching early.
    // Semantically safe: its griddepcontrol.wait still blocks until this
    // grid's memory is flushed.
    if (tid == 0) {
        asm volatile("griddepcontrol.launch_dependents;");
    }

    const float2* __restrict__ emb2 = (const float2*)emb;

    float2 acc = make_float2(0.0f, 0.0f);
    if (lane < 25) {
        #pragma unroll
        for (int i = 0; i < TOK_PER_WARP; i++) {
            int idx = sidx[wid * TOK_PER_WARP + i];
            if (idx >= 0 && idx < VOCAB) {
                float2 v = __ldg(&emb2[(size_t)idx * 25 + lane]);
                acc.x += v.x;
                acc.y += v.y;
            }
        }
        sred[wid][lane] = acc;
    }
    __syncthreads();

    // Warp 0: reduce 8 warps, project onto the two W rows, warp-reduce, store.
    if (tid < 32) {
        float d0 = 0.0f, d1 = 0.0f;
        if (tid < 25) {
            float2 p = make_float2(0.0f, 0.0f);
            #pragma unroll
            for (int w = 0; w < WARPS; w++) {
                p.x += sred[w][tid].x;
                p.y += sred[w][tid].y;
            }
            d0 = p.x * W[2 * tid]       + p.y * W[2 * tid + 1];       // row 0
            d1 = p.x * W[EMB + 2 * tid] + p.y * W[EMB + 2 * tid + 1]; // row 1
        }
        #pragma unroll
        for (int off = 16; off > 0; off >>= 1) {
            d0 += __shfl_down_sync(0xFFFFFFFFu, d0, off);
            d1 += __shfl_down_sync(0xFFFFFFFFu, d1, off);
        }
        if (tid == 0) {
            g_dots[((size_t)chunk * BATCH + b) * OUTD + 0] = d0;
            g_dots[((size_t)chunk * BATCH + b) * OUTD + 1] = d1;
        }
    }
}

// ---------------------------------------------------------------------------
// Kernel 2: sum chunk partials, /BATCH, +bias, ReLU.  1 block, 256 threads,
// thread tid handles (b = tid/2, o = tid%2). Launched with PDL so its ramp
// overlaps kernel 1; griddepcontrol.wait blocks until kernel 1's writes are
// visible.
// ---------------------------------------------------------------------------
__global__ void finalize_kernel(const float* __restrict__ bias,
                                float* __restrict__ out)
{
    // Wait for the primary grid's memory to be flushed before reading g_dots.
    asm volatile("griddepcontrol.wait;" ::: "memory");

    const int tid = threadIdx.x;      // [0,256)
    const int o   = tid & 1;

    float s = 0.0f;
    #pragma unroll
    for (int k = 0; k < NCHUNK; k++) {
        s += g_dots[(size_t)k * BATCH * OUTD + tid];
    }
    out[tid] = fmaxf(s * (1.0f / (float)BATCH) + bias[o], 0.0f);
}

// ---------------------------------------------------------------------------
// Inputs: t [128,2000] int32, embeddings [1e6,50] f32, W [2,50] f32, b [2] f32.
// Output: [128,2] f32.
// ---------------------------------------------------------------------------
extern "C" void kernel_launch(void* const* d_in, const int* in_sizes, int n_in,
                              void* d_out, int out_size)
{
    const int*   t   = (const int*)d_in[0];
    const float* emb = (const float*)d_in[1];
    const float* W   = (const float*)d_in[2];
    const float* bia = (const float*)d_in[3];
    float*       out = (float*)d_out;

    dim3 grid1(BATCH, NCHUNK);
    gather_kernel<<<grid1, 256>>>(t, emb, W);

    // Finalize with programmatic dependent launch (overlap its ramp with the
    // gather kernel's execution).
    cudaLaunchConfig_t cfg = {};
    cfg.gridDim  = dim3(1, 1, 1);
    cfg.blockDim = dim3(BATCH * OUTD, 1, 1);   // 256
    cfg.dynamicSmemBytes = 0;
    cfg.stream = 0;   // legacy default stream (same as <<<>>> above)

    cudaLaunchAttribute attrs[1];
    attrs[0].id = cudaLaunchAttributeProgrammaticStreamSerialization;
    attrs[0].val.programmaticStreamSerializationAllowed = 1;
    cfg.attrs    = attrs;
    cfg.numAttrs = 1;

    cudaLaunchKernelEx(&cfg, finalize_kernel, bia, out);
}

// round 8
// speedup vs baseline: 1.2875x; 1.0200x over previous
#include <cuda_runtime.h>
#include <cuda_bf16.h>
#include <cstdint>

#define VOCAB   1000000
#define EMB     50
#define OUTD    2
#define BATCH   128
#define SEQ     2000

#define NWARPS  32                  // 1024 threads per block
#define NTHREADS (NWARPS * 32)

// ---------------------------------------------------------------------------
// One block per batch row. Warp w processes tokens w, w+32, w+64, ... ;
// lanes 0-24 of each warp load the 50-float embedding row as 25 x float2.
// Block-level reduce -> [50 -> 2] projection -> /BATCH + bias + ReLU -> out.
// No inter-block communication at all.
// ---------------------------------------------------------------------------
__global__ __launch_bounds__(NTHREADS)
void fused_rowpool_kernel(const int* __restrict__ t,
                          const float* __restrict__ emb,
                          const float* __restrict__ W,
                          const float* __restrict__ bias,
                          float* __restrict__ out)
{
    const int b    = blockIdx.x;
    const int tid  = threadIdx.x;
    const int wid  = tid >> 5;
    const int lane = tid & 31;

    __shared__ int    sidx[SEQ];              // 8 KB
    __shared__ float2 sred[NWARPS][25];       // 6.4 KB

    // Stage this row's 2000 indices (coalesced, 2 per thread).
    const int* tp = t + (size_t)b * SEQ;
    #pragma unroll
    for (int i = tid; i < SEQ; i += NTHREADS) {
        sidx[i] = tp[i];
    }
    __syncthreads();

    const float2* __restrict__ emb2 = (const float2*)emb;

    float2 acc = make_float2(0.0f, 0.0f);
    if (lane < 25) {
        // 2000 / 32 = 62.5 -> warp handles 62 or 63 tokens.
        #pragma unroll 8
        for (int i = wid; i < SEQ; i += NWARPS) {
            int idx = sidx[i];
            if (idx >= 0 && idx < VOCAB) {
                float2 v = __ldg(&emb2[(size_t)idx * 25 + lane]);
                acc.x += v.x;
                acc.y += v.y;
            }
        }
        sred[wid][lane] = acc;
    }
    __syncthreads();

    // Warp 0: reduce the 32 warp partials, project onto W rows, finish.
    if (tid < 32) {
        float d0 = 0.0f, d1 = 0.0f;
        if (tid < 25) {
            float2 p = make_float2(0.0f, 0.0f);
            #pragma unroll
            for (int w = 0; w < NWARPS; w++) {
                p.x += sred[w][tid].x;
                p.y += sred[w][tid].y;
            }
            d0 = p.x * W[2 * tid]       + p.y * W[2 * tid + 1];       // W row 0
            d1 = p.x * W[EMB + 2 * tid] + p.y * W[EMB + 2 * tid + 1]; // W row 1
        }
        #pragma unroll
        for (int off = 16; off > 0; off >>= 1) {
            d0 += __shfl_down_sync(0xFFFFFFFFu, d0, off);
            d1 += __shfl_down_sync(0xFFFFFFFFu, d1, off);
        }
        if (tid == 0) {
            const float inv = 1.0f / (float)BATCH;
            out[b * OUTD + 0] = fmaxf(d0 * inv + bias[0], 0.0f);
            out[b * OUTD + 1] = fmaxf(d1 * inv + bias[1], 0.0f);
        }
    }
}

// ---------------------------------------------------------------------------
// Inputs: t [128,2000] int32, embeddings [1e6,50] f32, W [2,50] f32, b [2] f32.
// Output: [128,2] f32.
// ---------------------------------------------------------------------------
extern "C" void kernel_launch(void* const* d_in, const int* in_sizes, int n_in,
                              void* d_out, int out_size)
{
    const int*   t   = (const int*)d_in[0];
    const float* emb = (const float*)d_in[1];
    const float* W   = (const float*)d_in[2];
    const float* bia = (const float*)d_in[3];
    float*       out = (float*)d_out;

    fused_rowpool_kernel<<<BATCH, NTHREADS>>>(t, emb, W, bia, out);
}